// round 1
// baseline (speedup 1.0000x reference)
#include <cuda_runtime.h>

// Problem constants (match reference)
#define MAX_NODES 100000
#define DD 64

// Scratch for antisymmetric aggregation (atomics target). 25.6 MB static.
__device__ float g_agg[MAX_NODES * DD];

// ---------------------------------------------------------------------------
// zero the aggregation buffer (must run every launch; graph replays accumulate)
// ---------------------------------------------------------------------------
__global__ void __launch_bounds__(256) zero_agg_kernel(int n4) {
    int i = blockIdx.x * 256 + threadIdx.x;
    if (i < n4) {
        reinterpret_cast<float4*>(g_agg)[i] = make_float4(0.f, 0.f, 0.f, 0.f);
    }
}

// ---------------------------------------------------------------------------
// Block GEMM helpers. Block = 256 threads = 8 warps. Tile: 64 rows.
// Thread (tx = tid&31, ty = tid>>5) owns rows [ty*8, ty*8+8) and, for C=128
// layers, cols [tx*4, tx*4+4); for the C=64 layer, cols [tx*2, tx*2+2).
// Activations live in s_a (row-major, padded stride). Weights streamed through
// s_w in 64-row K-chunks (64x128 floats = 8192 = exactly the s_w size).
// ---------------------------------------------------------------------------

__device__ __forceinline__ void gemm_c128(
    const float* __restrict__ W,        // [K][128] row-major, K = nkc*64
    const float* __restrict__ s_a,      // activations [64][astride]
    float* __restrict__ s_w,            // 8192 floats
    int astride, int nkc, int tid, int r0, int c0, float acc[8][4])
{
    for (int kc = 0; kc < nkc; kc++) {
        __syncthreads();
        #pragma unroll
        for (int i = 0; i < 8; i++) {                 // 2048 float4 total
            int t  = tid + (i << 8);
            int k  = t >> 5;
            int c4 = (t & 31) << 2;
            *reinterpret_cast<float4*>(&s_w[k * 128 + c4]) =
                *reinterpret_cast<const float4*>(&W[(kc * 64 + k) * 128 + c4]);
        }
        __syncthreads();
        const float* ap = s_a + r0 * astride + kc * 64;
        #pragma unroll 4
        for (int k = 0; k < 64; k++) {
            float4 b = *reinterpret_cast<const float4*>(&s_w[k * 128 + c0]);
            #pragma unroll
            for (int i = 0; i < 8; i++) {
                float a = ap[i * astride + k];        // warp-broadcast LDS
                acc[i][0] = fmaf(a, b.x, acc[i][0]);
                acc[i][1] = fmaf(a, b.y, acc[i][1]);
                acc[i][2] = fmaf(a, b.z, acc[i][2]);
                acc[i][3] = fmaf(a, b.w, acc[i][3]);
            }
        }
    }
}

// bias + tanh, write hidden activations back into s_a (cols 0..127)
__device__ __forceinline__ void tanh_store(
    float acc[8][4], const float* __restrict__ bias,
    float* __restrict__ s_a, int astride, int r0, int c0)
{
    float4 bb = *reinterpret_cast<const float4*>(&bias[c0]);
    __syncthreads();   // all reads of previous s_a contents must be done
    #pragma unroll
    for (int i = 0; i < 8; i++) {
        float4 h;
        h.x = tanhf(acc[i][0] + bb.x);
        h.y = tanhf(acc[i][1] + bb.y);
        h.z = tanhf(acc[i][2] + bb.z);
        h.w = tanhf(acc[i][3] + bb.w);
        *reinterpret_cast<float4*>(&s_a[(r0 + i) * astride + c0]) = h;
    }
}

// final layer: K=128, C=64 (W3 fits entirely in s_w: 128*64 = 8192 floats)
__device__ __forceinline__ void gemm_c64(
    const float* __restrict__ W,
    const float* __restrict__ s_a, float* __restrict__ s_w,
    int astride, int tid, int r0, int cc, float acc[8][2])
{
    __syncthreads();
    #pragma unroll
    for (int i = 0; i < 8; i++) {
        int t = (tid + (i << 8)) << 2;
        *reinterpret_cast<float4*>(&s_w[t]) =
            *reinterpret_cast<const float4*>(&W[t]);
    }
    __syncthreads();
    const float* ap = s_a + r0 * astride;
    #pragma unroll 4
    for (int k = 0; k < 128; k++) {
        float2 b = *reinterpret_cast<const float2*>(&s_w[k * 64 + cc]);
        #pragma unroll
        for (int i = 0; i < 8; i++) {
            float a = ap[i * astride + k];
            acc[i][0] = fmaf(a, b.x, acc[i][0]);
            acc[i][1] = fmaf(a, b.y, acc[i][1]);
        }
    }
}

// ---------------------------------------------------------------------------
// Edge kernel: gather [edge_attr | x[recv] | x[send]] -> MLP -> LN
//              -> out2 = edge_attr + m, atomic scatter (+m recv, -m send)
// ---------------------------------------------------------------------------
#define EA_STRIDE 196   // 192 input cols + pad (keeps float4 alignment)

__global__ void __launch_bounds__(256) edge_kernel(
    const float* __restrict__ x, const int* __restrict__ senders,
    const int* __restrict__ receivers, const float* __restrict__ edge_attr,
    const float* __restrict__ W1, const float* __restrict__ b1,
    const float* __restrict__ W2, const float* __restrict__ b2,
    const float* __restrict__ W3, const float* __restrict__ b3,
    const float* __restrict__ gam, const float* __restrict__ bet,
    float* __restrict__ out2, int E)
{
    extern __shared__ float smem[];
    float* s_a = smem;                    // [64][196]
    float* s_w = smem + 64 * EA_STRIDE;   // 8192 floats

    const int tid = threadIdx.x;
    const int tx = tid & 31, ty = tid >> 5;
    const int r0 = ty * 8, c0 = tx * 4, cc = tx * 2;
    const int e0 = blockIdx.x * 64;

    // gather 64 rows x 48 float4 (edge_attr | x[recv] | x[send])
    #pragma unroll
    for (int it = 0; it < 12; it++) {
        int idx = tid + it * 256;
        int row = idx / 48;
        int k4  = idx - row * 48;
        int e   = min(e0 + row, E - 1);
        const float* src;
        if (k4 < 16)      src = edge_attr + (size_t)e * 64 + k4 * 4;
        else if (k4 < 32) src = x + (size_t)__ldg(receivers + e) * 64 + (k4 - 16) * 4;
        else              src = x + (size_t)__ldg(senders + e) * 64 + (k4 - 32) * 4;
        *reinterpret_cast<float4*>(&s_a[row * EA_STRIDE + k4 * 4]) =
            *reinterpret_cast<const float4*>(src);
    }
    // (gemm_c128 begins with __syncthreads -> gather visible)

    float acc[8][4];
    #pragma unroll
    for (int i = 0; i < 8; i++) { acc[i][0]=acc[i][1]=acc[i][2]=acc[i][3]=0.f; }
    gemm_c128(W1, s_a, s_w, EA_STRIDE, 3, tid, r0, c0, acc);     // K=192
    tanh_store(acc, b1, s_a, EA_STRIDE, r0, c0);

    #pragma unroll
    for (int i = 0; i < 8; i++) { acc[i][0]=acc[i][1]=acc[i][2]=acc[i][3]=0.f; }
    gemm_c128(W2, s_a, s_w, EA_STRIDE, 2, tid, r0, c0, acc);     // K=128
    tanh_store(acc, b2, s_a, EA_STRIDE, r0, c0);

    float acc3[8][2];
    #pragma unroll
    for (int i = 0; i < 8; i++) { acc3[i][0]=acc3[i][1]=0.f; }
    gemm_c64(W3, s_a, s_w, EA_STRIDE, tid, r0, cc, acc3);        // K=128, C=64

    const float bb0 = __ldg(&b3[cc]),  bb1 = __ldg(&b3[cc + 1]);
    const float g0  = __ldg(&gam[cc]), g1  = __ldg(&gam[cc + 1]);
    const float be0 = __ldg(&bet[cc]), be1 = __ldg(&bet[cc + 1]);

    #pragma unroll
    for (int i = 0; i < 8; i++) {
        int e = e0 + r0 + i;
        float v0 = acc3[i][0] + bb0;
        float v1 = acc3[i][1] + bb1;
        // row-wise LayerNorm over 64 cols: row lives entirely in this warp
        float s = v0 + v1;
        float q = v0 * v0 + v1 * v1;
        #pragma unroll
        for (int o = 16; o; o >>= 1) {
            s += __shfl_xor_sync(0xffffffffu, s, o);
            q += __shfl_xor_sync(0xffffffffu, q, o);
        }
        float mean = s * 0.015625f;                 // /64
        float var  = q * 0.015625f - mean * mean;
        float rstd = rsqrtf(var + 1e-5f);
        float m0 = (v0 - mean) * rstd * g0 + be0;
        float m1 = (v1 - mean) * rstd * g1 + be1;

        if (e < E) {
            float2 ea = *reinterpret_cast<const float2*>(&edge_attr[(size_t)e * 64 + cc]);
            float2 o2 = make_float2(ea.x + m0, ea.y + m1);
            *reinterpret_cast<float2*>(&out2[(size_t)e * 64 + cc]) = o2;
            int rr = __ldg(receivers + e);
            int ss = __ldg(senders + e);
            atomicAdd(&g_agg[rr * 64 + cc],      m0);
            atomicAdd(&g_agg[rr * 64 + cc + 1],  m1);
            atomicAdd(&g_agg[ss * 64 + cc],     -m0);
            atomicAdd(&g_agg[ss * 64 + cc + 1], -m1);
        }
    }
}

// ---------------------------------------------------------------------------
// Node kernel: gather [x | agg] -> MLP -> LN -> out1 = gx + x
// ---------------------------------------------------------------------------
#define NA_STRIDE 132   // 128 input cols + pad

__global__ void __launch_bounds__(256) node_kernel(
    const float* __restrict__ x,
    const float* __restrict__ W1, const float* __restrict__ b1,
    const float* __restrict__ W2, const float* __restrict__ b2,
    const float* __restrict__ W3, const float* __restrict__ b3,
    const float* __restrict__ gam, const float* __restrict__ bet,
    float* __restrict__ out1, int N)
{
    extern __shared__ float smem[];
    float* s_a = smem;                    // [64][132]
    float* s_w = smem + 64 * NA_STRIDE;   // 8192 floats

    const int tid = threadIdx.x;
    const int tx = tid & 31, ty = tid >> 5;
    const int r0 = ty * 8, c0 = tx * 4, cc = tx * 2;
    const int n0 = blockIdx.x * 64;

    // gather 64 rows x 32 float4 (x | agg); zero pad rows past N
    #pragma unroll
    for (int it = 0; it < 8; it++) {
        int idx = tid + it * 256;
        int row = idx >> 5;
        int k4  = idx & 31;
        int n   = n0 + row;
        float4 v = make_float4(0.f, 0.f, 0.f, 0.f);
        if (n < N) {
            const float* src = (k4 < 16)
                ? x     + (size_t)n * 64 + k4 * 4
                : g_agg + (size_t)n * 64 + (k4 - 16) * 4;
            v = *reinterpret_cast<const float4*>(src);
        }
        *reinterpret_cast<float4*>(&s_a[row * NA_STRIDE + k4 * 4]) = v;
    }

    float acc[8][4];
    #pragma unroll
    for (int i = 0; i < 8; i++) { acc[i][0]=acc[i][1]=acc[i][2]=acc[i][3]=0.f; }
    gemm_c128(W1, s_a, s_w, NA_STRIDE, 2, tid, r0, c0, acc);     // K=128
    tanh_store(acc, b1, s_a, NA_STRIDE, r0, c0);

    #pragma unroll
    for (int i = 0; i < 8; i++) { acc[i][0]=acc[i][1]=acc[i][2]=acc[i][3]=0.f; }
    gemm_c128(W2, s_a, s_w, NA_STRIDE, 2, tid, r0, c0, acc);     // K=128
    tanh_store(acc, b2, s_a, NA_STRIDE, r0, c0);

    float acc3[8][2];
    #pragma unroll
    for (int i = 0; i < 8; i++) { acc3[i][0]=acc3[i][1]=0.f; }
    gemm_c64(W3, s_a, s_w, NA_STRIDE, tid, r0, cc, acc3);        // K=128, C=64

    const float bb0 = __ldg(&b3[cc]),  bb1 = __ldg(&b3[cc + 1]);
    const float g0  = __ldg(&gam[cc]), g1  = __ldg(&gam[cc + 1]);
    const float be0 = __ldg(&bet[cc]), be1 = __ldg(&bet[cc + 1]);

    #pragma unroll
    for (int i = 0; i < 8; i++) {
        int n = n0 + r0 + i;
        float v0 = acc3[i][0] + bb0;
        float v1 = acc3[i][1] + bb1;
        float s = v0 + v1;
        float q = v0 * v0 + v1 * v1;
        #pragma unroll
        for (int o = 16; o; o >>= 1) {
            s += __shfl_xor_sync(0xffffffffu, s, o);
            q += __shfl_xor_sync(0xffffffffu, q, o);
        }
        float mean = s * 0.015625f;
        float var  = q * 0.015625f - mean * mean;
        float rstd = rsqrtf(var + 1e-5f);

        if (n < N) {
            float2 xv = *reinterpret_cast<const float2*>(&x[(size_t)n * 64 + cc]);
            float2 o1;
            o1.x = (v0 - mean) * rstd * g0 + be0 + xv.x;
            o1.y = (v1 - mean) * rstd * g1 + be1 + xv.y;
            *reinterpret_cast<float2*>(&out1[(size_t)n * 64 + cc]) = o1;
        }
    }
}

// ---------------------------------------------------------------------------
// launch
// ---------------------------------------------------------------------------
extern "C" void kernel_launch(void* const* d_in, const int* in_sizes, int n_in,
                              void* d_out, int out_size)
{
    const float* x         = (const float*)d_in[0];
    const int*   senders   = (const int*)  d_in[1];
    const int*   receivers = (const int*)  d_in[2];
    const float* edge_attr = (const float*)d_in[3];
    const float* ew1 = (const float*)d_in[4],  *eb1 = (const float*)d_in[5];
    const float* ew2 = (const float*)d_in[6],  *eb2 = (const float*)d_in[7];
    const float* ew3 = (const float*)d_in[8],  *eb3 = (const float*)d_in[9];
    const float* eg  = (const float*)d_in[10], *ebt = (const float*)d_in[11];
    const float* nw1 = (const float*)d_in[12], *nb1 = (const float*)d_in[13];
    const float* nw2 = (const float*)d_in[14], *nb2 = (const float*)d_in[15];
    const float* nw3 = (const float*)d_in[16], *nb3 = (const float*)d_in[17];
    const float* ng  = (const float*)d_in[18], *nbt = (const float*)d_in[19];

    const int N = in_sizes[0] / 64;   // x is [N, 64]
    const int E = in_sizes[1];        // senders is [E]

    float* out1 = (float*)d_out;                 // (gx + x)            [N,64]
    float* out2 = out1 + (size_t)N * 64;         // (edge_attr + msg)   [E,64]

    const size_t smem_e = (size_t)(64 * EA_STRIDE + 8192) * sizeof(float); // ~82.9 KB
    const size_t smem_n = (size_t)(64 * NA_STRIDE + 8192) * sizeof(float); // ~66.6 KB
    cudaFuncSetAttribute(edge_kernel, cudaFuncAttributeMaxDynamicSharedMemorySize, (int)smem_e);
    cudaFuncSetAttribute(node_kernel, cudaFuncAttributeMaxDynamicSharedMemorySize, (int)smem_n);

    const int agg4 = N * 16;   // N*64/4 float4s
    zero_agg_kernel<<<(agg4 + 255) / 256, 256>>>(agg4);

    edge_kernel<<<(E + 63) / 64, 256, smem_e>>>(
        x, senders, receivers, edge_attr,
        ew1, eb1, ew2, eb2, ew3, eb3, eg, ebt, out2, E);

    node_kernel<<<(N + 63) / 64, 256, smem_n>>>(
        x, nw1, nb1, nw2, nb2, nw3, nb3, ng, nbt, out1, N);
}

// round 2
// speedup vs baseline: 1.2936x; 1.2936x over previous
#include <cuda_runtime.h>
#include <cuda_bf16.h>
#include <cstdint>

#define MAX_NODES 100000

// scratch: antisymmetric aggregation target + pre-split transposed weights
__device__ float g_agg[MAX_NODES * 64];
__device__ __nv_bfloat16 g_wh[90112];
__device__ __nv_bfloat16 g_wl[90112];

#define OFF_EW1 0
#define OFF_EW2 24576
#define OFF_EW3 40960
#define OFF_NW1 49152
#define OFF_NW2 65536
#define OFF_NW3 81920

// ---------------------------------------------------------------------------
__global__ void __launch_bounds__(256) zero_agg_kernel(int n4) {
    int i = blockIdx.x * 256 + threadIdx.x;
    if (i < n4) reinterpret_cast<float4*>(g_agg)[i] = make_float4(0.f, 0.f, 0.f, 0.f);
}

// transpose W[k][n] -> Wt[n][k], split fp32 = bf16_hi + bf16_lo
__global__ void __launch_bounds__(256) prep_kernel(const float* __restrict__ W,
                                                   int K, int N, int off) {
    int idx = blockIdx.x * 256 + threadIdx.x;
    if (idx >= K * N) return;
    int n = idx / K, k = idx - n * K;
    float w = W[(size_t)k * N + n];
    __nv_bfloat16 h = __float2bfloat16_rn(w);
    g_wh[off + idx] = h;
    g_wl[off + idx] = __float2bfloat16_rn(w - __bfloat162float(h));
}

// ---------------------------------------------------------------------------
__device__ __forceinline__ void split2(float x, float y, uint32_t& h, uint32_t& l) {
    __nv_bfloat162 hh = __floats2bfloat162_rn(x, y);
    float rx = x - __bfloat162float(hh.x);
    float ry = y - __bfloat162float(hh.y);
    __nv_bfloat162 ll = __floats2bfloat162_rn(rx, ry);
    h = reinterpret_cast<uint32_t&>(hh);
    l = reinterpret_cast<uint32_t&>(ll);
}

__device__ __forceinline__ void mma16816(float* d, const uint32_t* a,
                                         uint32_t b0, uint32_t b1) {
    asm volatile(
        "mma.sync.aligned.m16n8k16.row.col.f32.bf16.bf16.f32 "
        "{%0,%1,%2,%3}, {%4,%5,%6,%7}, {%8,%9}, {%0,%1,%2,%3};\n"
        : "+f"(d[0]), "+f"(d[1]), "+f"(d[2]), "+f"(d[3])
        : "r"(a[0]), "r"(a[1]), "r"(a[2]), "r"(a[3]), "r"(b0), "r"(b1));
}

// ---------------------------------------------------------------------------
// C=128 layer. Block = 256 thr = 8 warps. M tile = 128 rows.
// warp w: nhalf = w&1 (64 cols), m-strips {(w>>1)*16, (w>>1)*16+64}.
// Weights streamed as [128 n][64 k] bf16 chunks, stride 72 (conflict-free).
// Activations: split bf16 in s_ah/s_al, row stride AS.
// ---------------------------------------------------------------------------
__device__ __forceinline__ void layer_c128(
    const __nv_bfloat16* __restrict__ Wh, const __nv_bfloat16* __restrict__ Wl,
    int K, __nv_bfloat16* s_ah, __nv_bfloat16* s_al, int AS,
    __nv_bfloat16* s_wh, __nv_bfloat16* s_wl,
    const float* __restrict__ bias, int tid)
{
    const int lane = tid & 31, w = tid >> 5;
    const int g = lane >> 2, t = lane & 3;
    const int nhalf = w & 1, mb0 = (w >> 1) << 4;
    float acc[2][8][4] = {};
    const int nkc = K >> 6;

    for (int kc = 0; kc < nkc; kc++) {
        __syncthreads();
        #pragma unroll
        for (int i = 0; i < 4; i++) {
            int idx = tid + (i << 8);
            int row = idx >> 3, k8 = (idx & 7) << 3;
            *reinterpret_cast<uint4*>(&s_wh[row * 72 + k8]) =
                *reinterpret_cast<const uint4*>(&Wh[row * K + (kc << 6) + k8]);
            *reinterpret_cast<uint4*>(&s_wl[row * 72 + k8]) =
                *reinterpret_cast<const uint4*>(&Wl[row * K + (kc << 6) + k8]);
        }
        __syncthreads();
        #pragma unroll
        for (int ks = 0; ks < 4; ks++) {
            const int ka = (kc << 6) + (ks << 4) + (t << 1);  // activation k
            const int kw = (ks << 4) + (t << 1);              // weight-chunk k
            uint32_t ah[2][4], al[2][4];
            #pragma unroll
            for (int s = 0; s < 2; s++) {
                int r = mb0 + (s << 6) + g;
                ah[s][0] = *reinterpret_cast<const uint32_t*>(&s_ah[r * AS + ka]);
                ah[s][1] = *reinterpret_cast<const uint32_t*>(&s_ah[(r + 8) * AS + ka]);
                ah[s][2] = *reinterpret_cast<const uint32_t*>(&s_ah[r * AS + ka + 8]);
                ah[s][3] = *reinterpret_cast<const uint32_t*>(&s_ah[(r + 8) * AS + ka + 8]);
                al[s][0] = *reinterpret_cast<const uint32_t*>(&s_al[r * AS + ka]);
                al[s][1] = *reinterpret_cast<const uint32_t*>(&s_al[(r + 8) * AS + ka]);
                al[s][2] = *reinterpret_cast<const uint32_t*>(&s_al[r * AS + ka + 8]);
                al[s][3] = *reinterpret_cast<const uint32_t*>(&s_al[(r + 8) * AS + ka + 8]);
            }
            #pragma unroll
            for (int nt = 0; nt < 8; nt++) {
                int n = (nhalf << 6) + (nt << 3) + g;
                uint32_t bh0 = *reinterpret_cast<const uint32_t*>(&s_wh[n * 72 + kw]);
                uint32_t bh1 = *reinterpret_cast<const uint32_t*>(&s_wh[n * 72 + kw + 8]);
                uint32_t bl0 = *reinterpret_cast<const uint32_t*>(&s_wl[n * 72 + kw]);
                uint32_t bl1 = *reinterpret_cast<const uint32_t*>(&s_wl[n * 72 + kw + 8]);
                #pragma unroll
                for (int s = 0; s < 2; s++) {
                    mma16816(acc[s][nt], ah[s], bh0, bh1);
                    mma16816(acc[s][nt], ah[s], bl0, bl1);
                    mma16816(acc[s][nt], al[s], bh0, bh1);
                }
            }
        }
    }
    // epilogue: bias + tanh, split-store back into s_ah/s_al
    __syncthreads();
    #pragma unroll
    for (int nt = 0; nt < 8; nt++) {
        int col = (nhalf << 6) + (nt << 3) + (t << 1);
        float2 bb = *reinterpret_cast<const float2*>(&bias[col]);
        #pragma unroll
        for (int s = 0; s < 2; s++) {
            int r = mb0 + (s << 6) + g;
            uint32_t h, l;
            split2(tanhf(acc[s][nt][0] + bb.x), tanhf(acc[s][nt][1] + bb.y), h, l);
            *reinterpret_cast<uint32_t*>(&s_ah[r * AS + col]) = h;
            *reinterpret_cast<uint32_t*>(&s_al[r * AS + col]) = l;
            split2(tanhf(acc[s][nt][2] + bb.x), tanhf(acc[s][nt][3] + bb.y), h, l);
            *reinterpret_cast<uint32_t*>(&s_ah[(r + 8) * AS + col]) = h;
            *reinterpret_cast<uint32_t*>(&s_al[(r + 8) * AS + col]) = l;
        }
    }
    __syncthreads();
}

// ---------------------------------------------------------------------------
// C=64 final layer (K=128). Weights [64 n][128 k], smem stride 136.
// Output: bias added, fp32 -> s_out (stride 68), pre-LayerNorm.
// ---------------------------------------------------------------------------
__device__ __forceinline__ void layer_c64(
    const __nv_bfloat16* __restrict__ Wh, const __nv_bfloat16* __restrict__ Wl,
    const __nv_bfloat16* s_ah, const __nv_bfloat16* s_al, int AS,
    __nv_bfloat16* s_wh, __nv_bfloat16* s_wl,
    const float* __restrict__ bias, float* s_out, int tid)
{
    const int lane = tid & 31, w = tid >> 5;
    const int g = lane >> 2, t = lane & 3;
    const int nhalf = w & 1, mb0 = (w >> 1) << 4;
    float acc[2][4][4] = {};

    __syncthreads();
    #pragma unroll
    for (int i = 0; i < 4; i++) {
        int idx = tid + (i << 8);
        int row = idx >> 4, k8 = (idx & 15) << 3;
        *reinterpret_cast<uint4*>(&s_wh[row * 136 + k8]) =
            *reinterpret_cast<const uint4*>(&Wh[row * 128 + k8]);
        *reinterpret_cast<uint4*>(&s_wl[row * 136 + k8]) =
            *reinterpret_cast<const uint4*>(&Wl[row * 128 + k8]);
    }
    __syncthreads();
    #pragma unroll
    for (int ks = 0; ks < 8; ks++) {
        const int ka = (ks << 4) + (t << 1);
        uint32_t ah[2][4], al[2][4];
        #pragma unroll
        for (int s = 0; s < 2; s++) {
            int r = mb0 + (s << 6) + g;
            ah[s][0] = *reinterpret_cast<const uint32_t*>(&s_ah[r * AS + ka]);
            ah[s][1] = *reinterpret_cast<const uint32_t*>(&s_ah[(r + 8) * AS + ka]);
            ah[s][2] = *reinterpret_cast<const uint32_t*>(&s_ah[r * AS + ka + 8]);
            ah[s][3] = *reinterpret_cast<const uint32_t*>(&s_ah[(r + 8) * AS + ka + 8]);
            al[s][0] = *reinterpret_cast<const uint32_t*>(&s_al[r * AS + ka]);
            al[s][1] = *reinterpret_cast<const uint32_t*>(&s_al[(r + 8) * AS + ka]);
            al[s][2] = *reinterpret_cast<const uint32_t*>(&s_al[r * AS + ka + 8]);
            al[s][3] = *reinterpret_cast<const uint32_t*>(&s_al[(r + 8) * AS + ka + 8]);
        }
        #pragma unroll
        for (int nt = 0; nt < 4; nt++) {
            int n = (nhalf << 5) + (nt << 3) + g;
            uint32_t bh0 = *reinterpret_cast<const uint32_t*>(&s_wh[n * 136 + ka]);
            uint32_t bh1 = *reinterpret_cast<const uint32_t*>(&s_wh[n * 136 + ka + 8]);
            uint32_t bl0 = *reinterpret_cast<const uint32_t*>(&s_wl[n * 136 + ka]);
            uint32_t bl1 = *reinterpret_cast<const uint32_t*>(&s_wl[n * 136 + ka + 8]);
            #pragma unroll
            for (int s = 0; s < 2; s++) {
                mma16816(acc[s][nt], ah[s], bh0, bh1);
                mma16816(acc[s][nt], ah[s], bl0, bl1);
                mma16816(acc[s][nt], al[s], bh0, bh1);
            }
        }
    }
    __syncthreads();  // done reading weights; s_out aliases the weight region
    #pragma unroll
    for (int nt = 0; nt < 4; nt++) {
        int col = (nhalf << 5) + (nt << 3) + (t << 1);
        float2 bb = *reinterpret_cast<const float2*>(&bias[col]);
        #pragma unroll
        for (int s = 0; s < 2; s++) {
            int r = mb0 + (s << 6) + g;
            *reinterpret_cast<float2*>(&s_out[r * 68 + col]) =
                make_float2(acc[s][nt][0] + bb.x, acc[s][nt][1] + bb.y);
            *reinterpret_cast<float2*>(&s_out[(r + 8) * 68 + col]) =
                make_float2(acc[s][nt][2] + bb.x, acc[s][nt][3] + bb.y);
        }
    }
    __syncthreads();
}

// ---------------------------------------------------------------------------
// Edge kernel: 128 edges/block
// ---------------------------------------------------------------------------
#define EAS 200

__global__ void __launch_bounds__(256) edge_kernel(
    const float* __restrict__ x, const int* __restrict__ senders,
    const int* __restrict__ receivers, const float* __restrict__ edge_attr,
    const float* __restrict__ b1, const float* __restrict__ b2,
    const float* __restrict__ b3, const float* __restrict__ gam,
    const float* __restrict__ bet, float* __restrict__ out2, int E)
{
    extern __shared__ char smem[];
    __nv_bfloat16* s_ah = reinterpret_cast<__nv_bfloat16*>(smem);
    __nv_bfloat16* s_al = s_ah + 128 * EAS;
    __nv_bfloat16* s_wh = s_al + 128 * EAS;
    __nv_bfloat16* s_wl = s_wh + 9216;
    float* s_out = reinterpret_cast<float*>(s_wh);

    const int tid = threadIdx.x;
    const int e0 = blockIdx.x << 7;

    // gather [edge_attr | x[recv] | x[send]] as split bf16
    #pragma unroll
    for (int it = 0; it < 24; it++) {
        int idx = tid + (it << 8);
        int row = idx / 48;
        int k4 = idx - row * 48;
        int e = min(e0 + row, E - 1);
        const float* src;
        if (k4 < 16)      src = edge_attr + (size_t)e * 64 + (k4 << 2);
        else if (k4 < 32) src = x + (size_t)__ldg(receivers + e) * 64 + ((k4 - 16) << 2);
        else              src = x + (size_t)__ldg(senders + e) * 64 + ((k4 - 32) << 2);
        float4 v = *reinterpret_cast<const float4*>(src);
        uint32_t h0, l0, h1, l1;
        split2(v.x, v.y, h0, l0);
        split2(v.z, v.w, h1, l1);
        int base = row * EAS + (k4 << 2);
        *reinterpret_cast<uint2*>(&s_ah[base]) = make_uint2(h0, h1);
        *reinterpret_cast<uint2*>(&s_al[base]) = make_uint2(l0, l1);
    }

    layer_c128(&g_wh[OFF_EW1], &g_wl[OFF_EW1], 192, s_ah, s_al, EAS, s_wh, s_wl, b1, tid);
    layer_c128(&g_wh[OFF_EW2], &g_wl[OFF_EW2], 128, s_ah, s_al, EAS, s_wh, s_wl, b2, tid);
    layer_c64 (&g_wh[OFF_EW3], &g_wl[OFF_EW3],      s_ah, s_al, EAS, s_wh, s_wl, b3, s_out, tid);

    // LayerNorm + residual out + antisymmetric scatter
    const int lane = tid & 31, w = tid >> 5;
    const int cc = lane << 1;
    const float g0 = __ldg(&gam[cc]), g1 = __ldg(&gam[cc + 1]);
    const float be0 = __ldg(&bet[cc]), be1 = __ldg(&bet[cc + 1]);
    #pragma unroll 4
    for (int i = 0; i < 16; i++) {
        int r = (w << 4) + i;
        int e = e0 + r;
        float2 v = *reinterpret_cast<const float2*>(&s_out[r * 68 + cc]);
        float s = v.x + v.y;
        float q = v.x * v.x + v.y * v.y;
        #pragma unroll
        for (int o = 16; o; o >>= 1) {
            s += __shfl_xor_sync(0xffffffffu, s, o);
            q += __shfl_xor_sync(0xffffffffu, q, o);
        }
        float mean = s * 0.015625f;
        float var = q * 0.015625f - mean * mean;
        float rstd = rsqrtf(var + 1e-5f);
        float m0 = (v.x - mean) * rstd * g0 + be0;
        float m1 = (v.y - mean) * rstd * g1 + be1;
        if (e < E) {
            float2 ea = *reinterpret_cast<const float2*>(&edge_attr[(size_t)e * 64 + cc]);
            *reinterpret_cast<float2*>(&out2[(size_t)e * 64 + cc]) =
                make_float2(ea.x + m0, ea.y + m1);
            int rr = __ldg(receivers + e);
            int sn = __ldg(senders + e);
            float* pr = &g_agg[rr * 64 + cc];
            float* ps = &g_agg[sn * 64 + cc];
            asm volatile("red.global.add.v2.f32 [%0], {%1, %2};"
                         :: "l"(pr), "f"(m0), "f"(m1) : "memory");
            asm volatile("red.global.add.v2.f32 [%0], {%1, %2};"
                         :: "l"(ps), "f"(-m0), "f"(-m1) : "memory");
        }
    }
}

// ---------------------------------------------------------------------------
// Node kernel: 128 nodes/block
// ---------------------------------------------------------------------------
#define NAS 136

__global__ void __launch_bounds__(256) node_kernel(
    const float* __restrict__ x,
    const float* __restrict__ b1, const float* __restrict__ b2,
    const float* __restrict__ b3, const float* __restrict__ gam,
    const float* __restrict__ bet, float* __restrict__ out1, int N)
{
    extern __shared__ char smem[];
    __nv_bfloat16* s_ah = reinterpret_cast<__nv_bfloat16*>(smem);
    __nv_bfloat16* s_al = s_ah + 128 * NAS;
    __nv_bfloat16* s_wh = s_al + 128 * NAS;
    __nv_bfloat16* s_wl = s_wh + 9216;
    float* s_out = reinterpret_cast<float*>(s_wh);

    const int tid = threadIdx.x;
    const int n0 = blockIdx.x << 7;

    // gather [x | agg] as split bf16 (zero-pad rows past N)
    #pragma unroll
    for (int it = 0; it < 16; it++) {
        int idx = tid + (it << 8);
        int row = idx >> 5;
        int k4 = idx & 31;
        int n = n0 + row;
        float4 v = make_float4(0.f, 0.f, 0.f, 0.f);
        if (n < N) {
            const float* src = (k4 < 16)
                ? x + (size_t)n * 64 + (k4 << 2)
                : g_agg + (size_t)n * 64 + ((k4 - 16) << 2);
            v = *reinterpret_cast<const float4*>(src);
        }
        uint32_t h0, l0, h1, l1;
        split2(v.x, v.y, h0, l0);
        split2(v.z, v.w, h1, l1);
        int base = row * NAS + (k4 << 2);
        *reinterpret_cast<uint2*>(&s_ah[base]) = make_uint2(h0, h1);
        *reinterpret_cast<uint2*>(&s_al[base]) = make_uint2(l0, l1);
    }

    layer_c128(&g_wh[OFF_NW1], &g_wl[OFF_NW1], 128, s_ah, s_al, NAS, s_wh, s_wl, b1, tid);
    layer_c128(&g_wh[OFF_NW2], &g_wl[OFF_NW2], 128, s_ah, s_al, NAS, s_wh, s_wl, b2, tid);
    layer_c64 (&g_wh[OFF_NW3], &g_wl[OFF_NW3],      s_ah, s_al, NAS, s_wh, s_wl, b3, s_out, tid);

    const int lane = tid & 31, w = tid >> 5;
    const int cc = lane << 1;
    const float g0 = __ldg(&gam[cc]), g1 = __ldg(&gam[cc + 1]);
    const float be0 = __ldg(&bet[cc]), be1 = __ldg(&bet[cc + 1]);
    #pragma unroll 4
    for (int i = 0; i < 16; i++) {
        int r = (w << 4) + i;
        int n = n0 + r;
        float2 v = *reinterpret_cast<const float2*>(&s_out[r * 68 + cc]);
        float s = v.x + v.y;
        float q = v.x * v.x + v.y * v.y;
        #pragma unroll
        for (int o = 16; o; o >>= 1) {
            s += __shfl_xor_sync(0xffffffffu, s, o);
            q += __shfl_xor_sync(0xffffffffu, q, o);
        }
        float mean = s * 0.015625f;
        float var = q * 0.015625f - mean * mean;
        float rstd = rsqrtf(var + 1e-5f);
        if (n < N) {
            float2 xv = *reinterpret_cast<const float2*>(&x[(size_t)n * 64 + cc]);
            float2 o1;
            o1.x = (v.x - mean) * rstd * g0 + be0 + xv.x;
            o1.y = (v.y - mean) * rstd * g1 + be1 + xv.y;
            *reinterpret_cast<float2*>(&out1[(size_t)n * 64 + cc]) = o1;
        }
    }
}

// ---------------------------------------------------------------------------
extern "C" void kernel_launch(void* const* d_in, const int* in_sizes, int n_in,
                              void* d_out, int out_size)
{
    const float* x         = (const float*)d_in[0];
    const int*   senders   = (const int*)  d_in[1];
    const int*   receivers = (const int*)  d_in[2];
    const float* edge_attr = (const float*)d_in[3];
    const float* ew1 = (const float*)d_in[4],  *eb1 = (const float*)d_in[5];
    const float* ew2 = (const float*)d_in[6],  *eb2 = (const float*)d_in[7];
    const float* ew3 = (const float*)d_in[8],  *eb3 = (const float*)d_in[9];
    const float* eg  = (const float*)d_in[10], *ebt = (const float*)d_in[11];
    const float* nw1 = (const float*)d_in[12], *nb1 = (const float*)d_in[13];
    const float* nw2 = (const float*)d_in[14], *nb2 = (const float*)d_in[15];
    const float* nw3 = (const float*)d_in[16], *nb3 = (const float*)d_in[17];
    const float* ng  = (const float*)d_in[18], *nbt = (const float*)d_in[19];

    const int N = in_sizes[0] / 64;
    const int E = in_sizes[1];

    float* out1 = (float*)d_out;
    float* out2 = out1 + (size_t)N * 64;

    // weight prep (transpose + bf16 split)
    prep_kernel<<<(192 * 128 + 255) / 256, 256>>>(ew1, 192, 128, OFF_EW1);
    prep_kernel<<<(128 * 128 + 255) / 256, 256>>>(ew2, 128, 128, OFF_EW2);
    prep_kernel<<<(128 *  64 + 255) / 256, 256>>>(ew3, 128,  64, OFF_EW3);
    prep_kernel<<<(128 * 128 + 255) / 256, 256>>>(nw1, 128, 128, OFF_NW1);
    prep_kernel<<<(128 * 128 + 255) / 256, 256>>>(nw2, 128, 128, OFF_NW2);
    prep_kernel<<<(128 *  64 + 255) / 256, 256>>>(nw3, 128,  64, OFF_NW3);

    const int agg4 = N * 16;
    zero_agg_kernel<<<(agg4 + 255) / 256, 256>>>(agg4);

    const size_t smem_e = (size_t)(128 * EAS * 2 + 18432) * sizeof(__nv_bfloat16); // 139264
    const size_t smem_n = (size_t)(128 * NAS * 2 + 18432) * sizeof(__nv_bfloat16); // 106496
    cudaFuncSetAttribute(edge_kernel, cudaFuncAttributeMaxDynamicSharedMemorySize, (int)smem_e);
    cudaFuncSetAttribute(node_kernel, cudaFuncAttributeMaxDynamicSharedMemorySize, (int)smem_n);

    edge_kernel<<<(E + 127) / 128, 256, smem_e>>>(
        x, senders, receivers, edge_attr, eb1, eb2, eb3, eg, ebt, out2, E);

    node_kernel<<<(N + 127) / 128, 256, smem_n>>>(
        x, nb1, nb2, nb3, ng, nbt, out1, N);
}

// round 4
// speedup vs baseline: 1.3926x; 1.0765x over previous
#include <cuda_runtime.h>
#include <cuda_bf16.h>
#include <cstdint>

#define MAX_NODES 100000

__device__ float g_agg[MAX_NODES * 64];
__device__ __nv_bfloat16 g_wh[90112];
__device__ __nv_bfloat16 g_wl[90112];

#define OFF_EW1 0
#define OFF_EW2 24576
#define OFF_EW3 40960
#define OFF_NW1 49152
#define OFF_NW2 65536
#define OFF_NW3 81920

// ---------------------------------------------------------------------------
__global__ void __launch_bounds__(256) zero_agg_kernel(int n4) {
    int i = blockIdx.x * 256 + threadIdx.x;
    if (i < n4) reinterpret_cast<float4*>(g_agg)[i] = make_float4(0.f, 0.f, 0.f, 0.f);
}
__global__ void pad_kernel() {}

// fused: transpose W[k][n] -> Wt[n][k], split fp32 = bf16_hi + bf16_lo
__global__ void __launch_bounds__(256) prep_kernel(
    const float* __restrict__ ew1, const float* __restrict__ ew2,
    const float* __restrict__ ew3, const float* __restrict__ nw1,
    const float* __restrict__ nw2, const float* __restrict__ nw3)
{
    int i = blockIdx.x * 256 + threadIdx.x;
    if (i >= 90112) return;
    const float* W; int K, N, li;
    if      (i < 24576) { W = ew1; K = 192; N = 128; li = i; }
    else if (i < 40960) { W = ew2; K = 128; N = 128; li = i - 24576; }
    else if (i < 49152) { W = ew3; K = 128; N = 64;  li = i - 40960; }
    else if (i < 65536) { W = nw1; K = 128; N = 128; li = i - 49152; }
    else if (i < 81920) { W = nw2; K = 128; N = 128; li = i - 65536; }
    else                { W = nw3; K = 128; N = 64;  li = i - 81920; }
    int n = li / K, k = li - n * K;
    float v = W[(size_t)k * N + n];
    __nv_bfloat16 h = __float2bfloat16_rn(v);
    g_wh[i] = h;
    g_wl[i] = __float2bfloat16_rn(v - __bfloat162float(h));
}

// ---------------------------------------------------------------------------
__device__ __forceinline__ uint32_t smem_u32(const void* p) {
    uint32_t a;
    asm("{ .reg .u64 t; cvta.to.shared.u64 t, %1; cvt.u32.u64 %0, t; }"
        : "=r"(a) : "l"(p));
    return a;
}

__device__ __forceinline__ void split2(float x, float y, uint32_t& h, uint32_t& l) {
    __nv_bfloat162 hh = __floats2bfloat162_rn(x, y);
    float rx = x - __bfloat162float(hh.x);
    float ry = y - __bfloat162float(hh.y);
    __nv_bfloat162 ll = __floats2bfloat162_rn(rx, ry);
    h = reinterpret_cast<uint32_t&>(hh);
    l = reinterpret_cast<uint32_t&>(ll);
}

__device__ __forceinline__ float tanhf_fast(float x) {
    float e;
    asm("ex2.approx.f32 %0, %1;" : "=f"(e) : "f"(x * 2.885390082f)); // exp(2x)
    return 1.0f - __fdividef(2.0f, e + 1.0f);
}

__device__ __forceinline__ void mma16816(float* d, const uint32_t* a,
                                         uint32_t b0, uint32_t b1) {
    asm volatile(
        "mma.sync.aligned.m16n8k16.row.col.f32.bf16.bf16.f32 "
        "{%0,%1,%2,%3}, {%4,%5,%6,%7}, {%8,%9}, {%0,%1,%2,%3};\n"
        : "+f"(d[0]), "+f"(d[1]), "+f"(d[2]), "+f"(d[3])
        : "r"(a[0]), "r"(a[1]), "r"(a[2]), "r"(a[3]), "r"(b0), "r"(b1));
}

__device__ __forceinline__ void ldm4(uint32_t* r, uint32_t addr) {
    asm volatile("ldmatrix.sync.aligned.m8n8.x4.shared.b16 {%0,%1,%2,%3}, [%4];"
                 : "=r"(r[0]), "=r"(r[1]), "=r"(r[2]), "=r"(r[3]) : "r"(addr));
}

#define CP16(dst, src) \
    asm volatile("cp.async.cg.shared.global [%0], [%1], 16;" \
                 :: "r"(dst), "l"(src) : "memory")
#define CP_WAIT() \
    asm volatile("cp.async.commit_group;\n cp.async.wait_group 0;" ::: "memory")

// ---------------------------------------------------------------------------
// C=128 layer. 256 thr = 8 warps, M tile = 128.
// warp w: nhalf = w&1 (64 n-cols), m-strips {(w>>1)*16, +64}.
// Weights staged [128n][72k-stride] via cp.async; fragments via ldmatrix.x4.
// ---------------------------------------------------------------------------
template <int K>
__device__ __forceinline__ void layer_c128(
    const __nv_bfloat16* __restrict__ Wh, const __nv_bfloat16* __restrict__ Wl,
    __nv_bfloat16* s_ah, __nv_bfloat16* s_al, int AS,
    __nv_bfloat16* s_wh, __nv_bfloat16* s_wl,
    const float* __restrict__ bias, int tid)
{
    const int lane = tid & 31, w = tid >> 5;
    const int g = lane >> 2, t = lane & 3;
    const int nhalf = w & 1, mb0 = (w >> 1) << 4;
    // ldmatrix per-thread address components
    const int aro = (lane & 7) + (((lane >> 3) & 1) << 3);
    const int ako = (lane >> 4) << 3;
    const int bro = (lane & 7) + ((lane >> 4) << 3);
    const int bko = ((lane >> 3) & 1) << 3;
    const uint32_t u_ah = smem_u32(s_ah), u_al = smem_u32(s_al);
    const uint32_t u_wh = smem_u32(s_wh), u_wl = smem_u32(s_wl);

    float acc[2][8][4] = {};

    #pragma unroll
    for (int kc = 0; kc < (K >> 6); kc++) {
        __syncthreads();
        {
            const __nv_bfloat16* sh = Wh + (kc << 6);
            const __nv_bfloat16* sl = Wl + (kc << 6);
            #pragma unroll
            for (int i = 0; i < 4; i++) {
                int idx = tid + (i << 8);          // 0..1023
                int n = idx >> 3, k8 = (idx & 7) << 3;
                CP16(u_wh + (uint32_t)(n * 72 + k8) * 2, sh + (size_t)n * K + k8);
                CP16(u_wl + (uint32_t)(n * 72 + k8) * 2, sl + (size_t)n * K + k8);
            }
            CP_WAIT();
        }
        __syncthreads();
        #pragma unroll
        for (int ks = 0; ks < 4; ks++) {
            const int ka = (kc << 6) + (ks << 4);
            const int kw = ks << 4;
            uint32_t ah[2][4], al[2][4];
            #pragma unroll
            for (int s = 0; s < 2; s++) {
                uint32_t aoff = (uint32_t)((mb0 + (s << 6) + aro) * AS + ka + ako) * 2;
                ldm4(ah[s], u_ah + aoff);
                ldm4(al[s], u_al + aoff);
            }
            #pragma unroll
            for (int np = 0; np < 4; np++) {
                int nb = (nhalf << 6) + (np << 4);
                uint32_t boff = (uint32_t)((nb + bro) * 72 + kw + bko) * 2;
                uint32_t bh[4], bl[4];
                ldm4(bh, u_wh + boff);
                ldm4(bl, u_wl + boff);
                #pragma unroll
                for (int s = 0; s < 2; s++) {
                    mma16816(acc[s][2 * np],     ah[s], bh[0], bh[1]);
                    mma16816(acc[s][2 * np],     ah[s], bl[0], bl[1]);
                    mma16816(acc[s][2 * np],     al[s], bh[0], bh[1]);
                    mma16816(acc[s][2 * np + 1], ah[s], bh[2], bh[3]);
                    mma16816(acc[s][2 * np + 1], ah[s], bl[2], bl[3]);
                    mma16816(acc[s][2 * np + 1], al[s], bh[2], bh[3]);
                }
            }
        }
    }
    // epilogue: bias + tanh, split-store back into s_ah/s_al
    __syncthreads();
    #pragma unroll
    for (int nt = 0; nt < 8; nt++) {
        int col = (nhalf << 6) + (nt << 3) + (t << 1);
        float2 bb = *reinterpret_cast<const float2*>(&bias[col]);
        #pragma unroll
        for (int s = 0; s < 2; s++) {
            int r = mb0 + (s << 6) + g;
            uint32_t h, l;
            split2(tanhf_fast(acc[s][nt][0] + bb.x), tanhf_fast(acc[s][nt][1] + bb.y), h, l);
            *reinterpret_cast<uint32_t*>(&s_ah[r * AS + col]) = h;
            *reinterpret_cast<uint32_t*>(&s_al[r * AS + col]) = l;
            split2(tanhf_fast(acc[s][nt][2] + bb.x), tanhf_fast(acc[s][nt][3] + bb.y), h, l);
            *reinterpret_cast<uint32_t*>(&s_ah[(r + 8) * AS + col]) = h;
            *reinterpret_cast<uint32_t*>(&s_al[(r + 8) * AS + col]) = l;
        }
    }
    __syncthreads();
}

// ---------------------------------------------------------------------------
// C=64 final layer, K=128. Weights [64n][136k-stride] fully staged.
// ---------------------------------------------------------------------------
__device__ __forceinline__ void layer_c64(
    const __nv_bfloat16* __restrict__ Wh, const __nv_bfloat16* __restrict__ Wl,
    const __nv_bfloat16* s_ah, const __nv_bfloat16* s_al, int AS,
    __nv_bfloat16* s_wh, __nv_bfloat16* s_wl,
    const float* __restrict__ bias, float* s_out, int tid)
{
    const int lane = tid & 31, w = tid >> 5;
    const int g = lane >> 2, t = lane & 3;
    const int nhalf = w & 1, mb0 = (w >> 1) << 4;
    const int aro = (lane & 7) + (((lane >> 3) & 1) << 3);
    const int ako = (lane >> 4) << 3;
    const int bro = (lane & 7) + ((lane >> 4) << 3);
    const int bko = ((lane >> 3) & 1) << 3;
    const uint32_t u_ah = smem_u32(s_ah), u_al = smem_u32(s_al);
    const uint32_t u_wh = smem_u32(s_wh), u_wl = smem_u32(s_wl);

    float acc[2][4][4] = {};

    __syncthreads();
    #pragma unroll
    for (int i = 0; i < 4; i++) {
        int idx = tid + (i << 8);                  // 0..1023
        int n = idx >> 4, k8 = (idx & 15) << 3;
        CP16(u_wh + (uint32_t)(n * 136 + k8) * 2, Wh + (size_t)n * 128 + k8);
        CP16(u_wl + (uint32_t)(n * 136 + k8) * 2, Wl + (size_t)n * 128 + k8);
    }
    CP_WAIT();
    __syncthreads();

    #pragma unroll
    for (int ks = 0; ks < 8; ks++) {
        const int ka = ks << 4;
        uint32_t ah[2][4], al[2][4];
        #pragma unroll
        for (int s = 0; s < 2; s++) {
            uint32_t aoff = (uint32_t)((mb0 + (s << 6) + aro) * AS + ka + ako) * 2;
            ldm4(ah[s], u_ah + aoff);
            ldm4(al[s], u_al + aoff);
        }
        #pragma unroll
        for (int np = 0; np < 2; np++) {
            int nb = (nhalf << 5) + (np << 4);
            uint32_t boff = (uint32_t)((nb + bro) * 136 + ka + bko) * 2;
            uint32_t bh[4], bl[4];
            ldm4(bh, u_wh + boff);
            ldm4(bl, u_wl + boff);
            #pragma unroll
            for (int s = 0; s < 2; s++) {
                mma16816(acc[s][2 * np],     ah[s], bh[0], bh[1]);
                mma16816(acc[s][2 * np],     ah[s], bl[0], bl[1]);
                mma16816(acc[s][2 * np],     al[s], bh[0], bh[1]);
                mma16816(acc[s][2 * np + 1], ah[s], bh[2], bh[3]);
                mma16816(acc[s][2 * np + 1], ah[s], bl[2], bl[3]);
                mma16816(acc[s][2 * np + 1], al[s], bh[2], bh[3]);
            }
        }
    }
    __syncthreads();  // done reading weights; s_out aliases the weight region
    #pragma unroll
    for (int nt = 0; nt < 4; nt++) {
        int col = (nhalf << 5) + (nt << 3) + (t << 1);
        float2 bb = *reinterpret_cast<const float2*>(&bias[col]);
        #pragma unroll
        for (int s = 0; s < 2; s++) {
            int r = mb0 + (s << 6) + g;
            *reinterpret_cast<float2*>(&s_out[r * 68 + col]) =
                make_float2(acc[s][nt][0] + bb.x, acc[s][nt][1] + bb.y);
            *reinterpret_cast<float2*>(&s_out[(r + 8) * 68 + col]) =
                make_float2(acc[s][nt][2] + bb.x, acc[s][nt][3] + bb.y);
        }
    }
    __syncthreads();
}

// ---------------------------------------------------------------------------
// Edge kernel: 128 edges/block
// ---------------------------------------------------------------------------
#define EAS 200

__global__ void __launch_bounds__(256) edge_kernel(
    const float* __restrict__ x, const int* __restrict__ senders,
    const int* __restrict__ receivers, const float* __restrict__ edge_attr,
    const float* __restrict__ b1, const float* __restrict__ b2,
    const float* __restrict__ b3, const float* __restrict__ gam,
    const float* __restrict__ bet, float* __restrict__ out2, int E)
{
    extern __shared__ char smem[];
    __nv_bfloat16* s_ah = reinterpret_cast<__nv_bfloat16*>(smem);
    __nv_bfloat16* s_al = s_ah + 128 * EAS;
    __nv_bfloat16* s_wh = s_al + 128 * EAS;
    __nv_bfloat16* s_wl = s_wh + 9216;
    float* s_out = reinterpret_cast<float*>(s_wh);

    const int tid = threadIdx.x;
    const int e0 = blockIdx.x << 7;

    #pragma unroll
    for (int it = 0; it < 24; it++) {
        int idx = tid + (it << 8);
        int row = idx / 48;
        int k4 = idx - row * 48;
        int e = min(e0 + row, E - 1);
        const float* src;
        if (k4 < 16)      src = edge_attr + (size_t)e * 64 + (k4 << 2);
        else if (k4 < 32) src = x + (size_t)__ldg(receivers + e) * 64 + ((k4 - 16) << 2);
        else              src = x + (size_t)__ldg(senders + e) * 64 + ((k4 - 32) << 2);
        float4 v = *reinterpret_cast<const float4*>(src);
        uint32_t h0, l0, h1, l1;
        split2(v.x, v.y, h0, l0);
        split2(v.z, v.w, h1, l1);
        int base = row * EAS + (k4 << 2);
        *reinterpret_cast<uint2*>(&s_ah[base]) = make_uint2(h0, h1);
        *reinterpret_cast<uint2*>(&s_al[base]) = make_uint2(l0, l1);
    }

    layer_c128<192>(&g_wh[OFF_EW1], &g_wl[OFF_EW1], s_ah, s_al, EAS, s_wh, s_wl, b1, tid);
    layer_c128<128>(&g_wh[OFF_EW2], &g_wl[OFF_EW2], s_ah, s_al, EAS, s_wh, s_wl, b2, tid);
    layer_c64(&g_wh[OFF_EW3], &g_wl[OFF_EW3], s_ah, s_al, EAS, s_wh, s_wl, b3, s_out, tid);

    // LayerNorm + residual + antisymmetric scatter
    const int lane = tid & 31, w = tid >> 5;
    const int cc = lane << 1;
    const float g0 = __ldg(&gam[cc]), g1 = __ldg(&gam[cc + 1]);
    const float be0 = __ldg(&bet[cc]), be1 = __ldg(&bet[cc + 1]);
    #pragma unroll 4
    for (int i = 0; i < 16; i++) {
        int r = (w << 4) + i;
        int e = e0 + r;
        float2 v = *reinterpret_cast<const float2*>(&s_out[r * 68 + cc]);
        float s = v.x + v.y;
        float q = v.x * v.x + v.y * v.y;
        #pragma unroll
        for (int o = 16; o; o >>= 1) {
            s += __shfl_xor_sync(0xffffffffu, s, o);
            q += __shfl_xor_sync(0xffffffffu, q, o);
        }
        float mean = s * 0.015625f;
        float var = q * 0.015625f - mean * mean;
        float rstd = rsqrtf(var + 1e-5f);
        float m0 = (v.x - mean) * rstd * g0 + be0;
        float m1 = (v.y - mean) * rstd * g1 + be1;
        if (e < E) {
            float2 ea = *reinterpret_cast<const float2*>(&edge_attr[(size_t)e * 64 + cc]);
            *reinterpret_cast<float2*>(&out2[(size_t)e * 64 + cc]) =
                make_float2(ea.x + m0, ea.y + m1);
            int rr = __ldg(receivers + e);
            int sn = __ldg(senders + e);
            float* pr = &g_agg[rr * 64 + cc];
            float* ps = &g_agg[sn * 64 + cc];
            asm volatile("red.global.add.v2.f32 [%0], {%1, %2};"
                         :: "l"(pr), "f"(m0), "f"(m1) : "memory");
            asm volatile("red.global.add.v2.f32 [%0], {%1, %2};"
                         :: "l"(ps), "f"(-m0), "f"(-m1) : "memory");
        }
    }
}

// ---------------------------------------------------------------------------
// Node kernel: 128 nodes/block
// ---------------------------------------------------------------------------
#define NAS 136

__global__ void __launch_bounds__(256) node_kernel(
    const float* __restrict__ x,
    const float* __restrict__ b1, const float* __restrict__ b2,
    const float* __restrict__ b3, const float* __restrict__ gam,
    const float* __restrict__ bet, float* __restrict__ out1, int N)
{
    extern __shared__ char smem[];
    __nv_bfloat16* s_ah = reinterpret_cast<__nv_bfloat16*>(smem);
    __nv_bfloat16* s_al = s_ah + 128 * NAS;
    __nv_bfloat16* s_wh = s_al + 128 * NAS;
    __nv_bfloat16* s_wl = s_wh + 9216;
    float* s_out = reinterpret_cast<float*>(s_wh);

    const int tid = threadIdx.x;
    const int n0 = blockIdx.x << 7;

    #pragma unroll
    for (int it = 0; it < 16; it++) {
        int idx = tid + (it << 8);
        int row = idx >> 5;
        int k4 = idx & 31;
        int n = n0 + row;
        float4 v = make_float4(0.f, 0.f, 0.f, 0.f);
        if (n < N) {
            const float* src = (k4 < 16)
                ? x + (size_t)n * 64 + (k4 << 2)
                : g_agg + (size_t)n * 64 + ((k4 - 16) << 2);
            v = *reinterpret_cast<const float4*>(src);
        }
        uint32_t h0, l0, h1, l1;
        split2(v.x, v.y, h0, l0);
        split2(v.z, v.w, h1, l1);
        int base = row * NAS + (k4 << 2);
        *reinterpret_cast<uint2*>(&s_ah[base]) = make_uint2(h0, h1);
        *reinterpret_cast<uint2*>(&s_al[base]) = make_uint2(l0, l1);
    }

    layer_c128<128>(&g_wh[OFF_NW1], &g_wl[OFF_NW1], s_ah, s_al, NAS, s_wh, s_wl, b1, tid);
    layer_c128<128>(&g_wh[OFF_NW2], &g_wl[OFF_NW2], s_ah, s_al, NAS, s_wh, s_wl, b2, tid);
    layer_c64(&g_wh[OFF_NW3], &g_wl[OFF_NW3], s_ah, s_al, NAS, s_wh, s_wl, b3, s_out, tid);

    const int lane = tid & 31, w = tid >> 5;
    const int cc = lane << 1;
    const float g0 = __ldg(&gam[cc]), g1 = __ldg(&gam[cc + 1]);
    const float be0 = __ldg(&bet[cc]), be1 = __ldg(&bet[cc + 1]);
    #pragma unroll 4
    for (int i = 0; i < 16; i++) {
        int r = (w << 4) + i;
        int n = n0 + r;
        float2 v = *reinterpret_cast<const float2*>(&s_out[r * 68 + cc]);
        float s = v.x + v.y;
        float q = v.x * v.x + v.y * v.y;
        #pragma unroll
        for (int o = 16; o; o >>= 1) {
            s += __shfl_xor_sync(0xffffffffu, s, o);
            q += __shfl_xor_sync(0xffffffffu, q, o);
        }
        float mean = s * 0.015625f;
        float var = q * 0.015625f - mean * mean;
        float rstd = rsqrtf(var + 1e-5f);
        if (n < N) {
            float2 xv = *reinterpret_cast<const float2*>(&x[(size_t)n * 64 + cc]);
            float2 o1;
            o1.x = (v.x - mean) * rstd * g0 + be0 + xv.x;
            o1.y = (v.y - mean) * rstd * g1 + be1 + xv.y;
            *reinterpret_cast<float2*>(&out1[(size_t)n * 64 + cc]) = o1;
        }
    }
}

// ---------------------------------------------------------------------------
extern "C" void kernel_launch(void* const* d_in, const int* in_sizes, int n_in,
                              void* d_out, int out_size)
{
    const float* x         = (const float*)d_in[0];
    const int*   senders   = (const int*)  d_in[1];
    const int*   receivers = (const int*)  d_in[2];
    const float* edge_attr = (const float*)d_in[3];
    const float* ew1 = (const float*)d_in[4],  *eb1 = (const float*)d_in[5];
    const float* ew2 = (const float*)d_in[6],  *eb2 = (const float*)d_in[7];
    const float* ew3 = (const float*)d_in[8],  *eb3 = (const float*)d_in[9];
    const float* eg  = (const float*)d_in[10], *ebt = (const float*)d_in[11];
    const float* nw1 = (const float*)d_in[12], *nb1 = (const float*)d_in[13];
    const float* nw2 = (const float*)d_in[14], *nb2 = (const float*)d_in[15];
    const float* nw3 = (const float*)d_in[16], *nb3 = (const float*)d_in[17];
    const float* ng  = (const float*)d_in[18], *nbt = (const float*)d_in[19];

    const int N = in_sizes[0] / 64;
    const int E = in_sizes[1];

    float* out1 = (float*)d_out;
    float* out2 = out1 + (size_t)N * 64;

    const size_t smem_e = (size_t)(128 * EAS * 2 + 18432) * sizeof(__nv_bfloat16);
    const size_t smem_n = (size_t)(128 * NAS * 2 + 18432) * sizeof(__nv_bfloat16);
    cudaFuncSetAttribute(edge_kernel, cudaFuncAttributeMaxDynamicSharedMemorySize, (int)smem_e);
    cudaFuncSetAttribute(node_kernel, cudaFuncAttributeMaxDynamicSharedMemorySize, (int)smem_n);

    // 5 launches before edge_kernel so ncu (-s 5 -c 1) profiles edge_kernel
    prep_kernel<<<(90112 + 255) / 256, 256>>>(ew1, ew2, ew3, nw1, nw2, nw3);
    zero_agg_kernel<<<(N * 16 + 255) / 256, 256>>>(N * 16);
    pad_kernel<<<1, 32>>>();
    pad_kernel<<<1, 32>>>();
    pad_kernel<<<1, 32>>>();

    edge_kernel<<<(E + 127) / 128, 256, smem_e>>>(
        x, senders, receivers, edge_attr, eb1, eb2, eb3, eg, ebt, out2, E);

    node_kernel<<<(N + 127) / 128, 256, smem_n>>>(
        x, nb1, nb2, nb3, ng, nbt, out1, N);
}